// round 17
// baseline (speedup 1.0000x reference)
#include <cuda_runtime.h>
#include <cstdint>

// Problem constants
#define BSZ   2048
#define DIM   1024
#define DWM   512
#define WIN   256
#define NH    8
#define HD    64
#define QKV_LD 1536
#define ATT_SCALE 0.125f

// Scratch (device globals: allocation-free rule)
__device__ float g_qkv[(size_t)BSZ * QKV_LD];   // 12 MB
__device__ float g_att[(size_t)BSZ * DWM];      // 4 MB (tf32-valued)
__device__ int   g_rows[BSZ];                   // permutation: non-reset first
__device__ int   g_nrows;                       // count of non-reset rows
// tf32-pre-rounded operands
__device__ float g_xt [(size_t)BSZ * DIM];      // 8 MB
__device__ float g_wqt[(size_t)DWM * DIM];      // 2 MB
__device__ float g_wkt[(size_t)DWM * DIM];
__device__ float g_wvt[(size_t)DWM * DIM];
__device__ float g_wot[(size_t)DIM * DWM];

// ---------------- bool dtype helpers ------------------------------------------
__device__ __forceinline__ int bool_mode(const unsigned char* valid)
{
    unsigned char b0 = valid[0], b1 = valid[1];
    return (b0 == 0) ? 2 : (b1 != 0 ? 0 : 1);   // 0=u8, 1=i32, 2=f32
}
__device__ __forceinline__ bool read_bool(const void* p, long idx, int mode)
{
    if (mode == 1) return ((const int*)p)[idx] != 0;
    if (mode == 2) return ((const float*)p)[idx] != 0.0f;
    return ((const unsigned char*)p)[idx] != 0;
}

// ---------------- tf32 helpers ------------------------------------------------
__device__ __forceinline__ uint32_t f2tf32(float f) {
    uint32_t u;
    asm("cvt.rna.tf32.f32 %0, %1;" : "=r"(u) : "f"(f));
    return u;
}
__device__ __forceinline__ void mma_tf32(float* d, const uint32_t* a, const uint32_t* b) {
    asm volatile(
        "mma.sync.aligned.m16n8k8.row.col.f32.tf32.tf32.f32 "
        "{%0,%1,%2,%3},{%4,%5,%6,%7},{%8,%9},{%0,%1,%2,%3};\n"
        : "+f"(d[0]), "+f"(d[1]), "+f"(d[2]), "+f"(d[3])
        : "r"(a[0]), "r"(a[1]), "r"(a[2]), "r"(a[3]), "r"(b[0]), "r"(b[1]));
}
__device__ __forceinline__ void cp16(uint32_t dst_smem, const void* src) {
    asm volatile("cp.async.cg.shared.global [%0], [%1], 16;"
                 :: "r"(dst_smem), "l"(src));
}

// ---------------- convert + compaction (fused, one launch) --------------------
#define X_F4  (BSZ * DIM / 4)     // 524288
#define W_F4  (DWM * DIM / 4)     // 131072
__global__ __launch_bounds__(256) void convert_kernel(
    const float* __restrict__ x,  const float* __restrict__ wq,
    const float* __restrict__ wk, const float* __restrict__ wv,
    const float* __restrict__ wo,
    const void* __restrict__ resetIn, const void* __restrict__ validIn)
{
    if (blockIdx.x == 2048) {
        // ---- compaction: permutation, non-reset rows first ----
        __shared__ int wsum_s[8];
        __shared__ int total_s;
        const int t    = threadIdx.x;
        const int lane = t & 31;
        const int wid  = t >> 5;
        const int mode = bool_mode((const unsigned char*)validIn);

        bool nr[8];
        int cnt = 0;
        #pragma unroll
        for (int j = 0; j < 8; ++j) {
            nr[j] = !read_bool(resetIn, 8 * t + j, mode);
            cnt += (int)nr[j];
        }
        int incl = cnt;
        #pragma unroll
        for (int o = 1; o < 32; o <<= 1) {
            int v = __shfl_up_sync(0xffffffffu, incl, o);
            if (lane >= o) incl += v;
        }
        if (lane == 31) wsum_s[wid] = incl;
        __syncthreads();
        if (t < 8) {
            int v = wsum_s[t];
            #pragma unroll
            for (int o = 1; o < 8; o <<= 1) {
                int u = __shfl_up_sync(0xffu, v, o);
                if (t >= o) v += u;
            }
            wsum_s[t] = v;
            if (t == 7) total_s = v;
        }
        __syncthreads();
        int base = (wid > 0) ? wsum_s[wid - 1] : 0;
        int excl = base + incl - cnt;
        const int total = total_s;
        int posn = excl;
        int posr = total + (8 * t - excl);
        #pragma unroll
        for (int j = 0; j < 8; ++j) {
            if (nr[j]) g_rows[posn++] = 8 * t + j;
            else       g_rows[posr++] = 8 * t + j;
        }
        if (t == 0) g_nrows = total;
        return;
    }

    // ---- conversion ----
    const int gid = blockIdx.x * 256 + threadIdx.x;
    #pragma unroll
    for (int rep = 0; rep < 2; ++rep) {
        int i = gid + rep * 524288;
        const float4* s; uint4* d; int off;
        if (i < X_F4)                 { s = (const float4*)x;  d = (uint4*)g_xt;  off = i; }
        else if (i < X_F4 + W_F4)     { s = (const float4*)wq; d = (uint4*)g_wqt; off = i - X_F4; }
        else if (i < X_F4 + 2*W_F4)   { s = (const float4*)wk; d = (uint4*)g_wkt; off = i - X_F4 - W_F4; }
        else if (i < X_F4 + 3*W_F4)   { s = (const float4*)wv; d = (uint4*)g_wvt; off = i - X_F4 - 2*W_F4; }
        else                          { s = (const float4*)wo; d = (uint4*)g_wot; off = i - X_F4 - 3*W_F4; }
        float4 v = s[off];
        uint4 t;
        t.x = f2tf32(v.x); t.y = f2tf32(v.y); t.z = f2tf32(v.z); t.w = f2tf32(v.w);
        d[off] = t;
    }
}

// ===================== tf32 mma.sync GEMM, BK=64 / 2-stage cp.async ===========
// C[m,n] = sum_k A[m,k]*B[n,k] + bias[n]; A,B pre-rounded to tf32 values.
// CTA tile 128x128, K-tile 64, 256 threads = 8 warps (2m x 4n), warp tile 64x32.
// Same XOR-swizzled layout (row stride 64 floats ≡ 0 mod 32 banks ->
// identical conflict-free proof); half the syncs/waits of the BK=32 version.
#define BM 128
#define BN 128
#define BK 64
#define NSTAGE 2
#define A_FL (BM * BK)                    // 8192 floats
#define B_FL (BN * BK)                    // 8192
#define STAGE_FLOATS (A_FL + B_FL)        // 16384
#define STAGE_BYTES  (STAGE_FLOATS * 4)   // 65536
#define TCSM_BYTES   (NSTAGE * STAGE_BYTES)  // 131072 (opt-in)

template<bool GATHER>
__device__ __forceinline__ void tc_gemm_body(
    const float* __restrict__ A, const float* __restrict__ Bw,
    const float* __restrict__ bias, float* __restrict__ C,
    int K, int ldc, int rowBase, int colB, int colC, int niter, int nrows)
{
    extern __shared__ float smem[];
    __shared__ int ridx_s[BM];

    const int tid  = threadIdx.x;
    const int lane = tid & 31;
    const int warp = tid >> 5;
    const int g    = lane >> 2;          // 0..7
    const int tg   = lane & 3;           // 0..3
    const int wm   = (warp >> 2) * 64;   // 0,64
    const int wn   = (warp & 3) * 32;    // 0,32,64,96

    if (GATHER) {
        if (tid < BM) {
            int rr = rowBase + tid;
            ridx_s[tid] = (rr < nrows) ? g_rows[rr] : 0;
        }
        __syncthreads();
    }

    const float* Bbase = Bw + (size_t)colB * K;
    const uint32_t smem_u = (uint32_t)__cvta_generic_to_shared(smem);

    float acc[4][4][4];
    #pragma unroll
    for (int mt = 0; mt < 4; ++mt)
        #pragma unroll
        for (int nt = 0; nt < 4; ++nt)
            #pragma unroll
            for (int r = 0; r < 4; ++r) acc[mt][nt][r] = 0.f;

    auto arow = [&](int row) -> const float* {
        int rr = GATHER ? ridx_s[row] : (rowBase + row);
        return A + (size_t)rr * K;
    };
    // one tile = 128x64 A + 128x64 B; 2048 float4 each; 8 cp16/thread per operand
    auto issue_tile = [&](int stage, int ko) {
        uint32_t abase = smem_u + stage * STAGE_BYTES;
        uint32_t bbase = abase + A_FL * 4;
        #pragma unroll
        for (int i = 0; i < 8; ++i) {
            int idx = tid + (i << 8), row = idx >> 4, q = idx & 15;
            uint32_t soff = (uint32_t)(row * BK + ((q ^ (row & 7)) << 2)) * 4u;
            cp16(abase + soff, arow(row) + ko + (q << 2));
            cp16(bbase + soff, Bbase + (size_t)row * K + ko + (q << 2));
        }
        asm volatile("cp.async.commit_group;");
    };

    issue_tile(0, 0);   // prologue: tile 0

    for (int it = 0; it < niter; ++it) {
        asm volatile("cp.async.wait_group 0;");
        __syncthreads();

        if (it + 1 < niter)
            issue_tile((it + 1) & 1, (it + 1) * BK);

        const uint32_t* Abuf = (const uint32_t*)(smem + (it & 1) * STAGE_FLOATS);
        const uint32_t* Bbuf = Abuf + A_FL;
        #pragma unroll
        for (int ks = 0; ks < 8; ++ks) {
            uint32_t af[4][4], bf[4][2];
            const int g0 = ((2 * ks) ^ g) << 2;
            const int g1 = ((2 * ks + 1) ^ g) << 2;
            #pragma unroll
            for (int mt = 0; mt < 4; ++mt) {
                int r0 = wm + mt * 16 + g;
                int r1 = r0 + 8;
                af[mt][0] = Abuf[r0 * BK + g0 + tg];
                af[mt][1] = Abuf[r1 * BK + g0 + tg];
                af[mt][2] = Abuf[r0 * BK + g1 + tg];
                af[mt][3] = Abuf[r1 * BK + g1 + tg];
            }
            #pragma unroll
            for (int nt = 0; nt < 4; ++nt) {
                int n = wn + nt * 8 + g;
                bf[nt][0] = Bbuf[n * BK + g0 + tg];
                bf[nt][1] = Bbuf[n * BK + g1 + tg];
            }
            #pragma unroll
            for (int mt = 0; mt < 4; ++mt)
                #pragma unroll
                for (int nt = 0; nt < 4; ++nt)
                    mma_tf32(acc[mt][nt], af[mt], bf[nt]);
        }
    }

    // ---- epilogue: C = acc + bias ----
    #pragma unroll
    for (int mt = 0; mt < 4; ++mt) {
        #pragma unroll
        for (int nt = 0; nt < 4; ++nt) {
            int lr0 = wm + mt * 16 + g;
            int lr1 = lr0 + 8;
            int col = wn + nt * 8 + tg * 2;
            float b0 = bias[colB + col], b1 = bias[colB + col + 1];
            float2 v0 = make_float2(acc[mt][nt][0] + b0, acc[mt][nt][1] + b1);
            float2 v1 = make_float2(acc[mt][nt][2] + b0, acc[mt][nt][3] + b1);
            if (GATHER) {
                if (rowBase + lr0 < nrows)
                    *(float2*)(C + (size_t)ridx_s[lr0] * ldc + colC + col) = v0;
                if (rowBase + lr1 < nrows)
                    *(float2*)(C + (size_t)ridx_s[lr1] * ldc + colC + col) = v1;
            } else {
                *(float2*)(C + (size_t)(rowBase + lr0) * ldc + colC + col) = v0;
                *(float2*)(C + (size_t)(rowBase + lr1) * ldc + colC + col) = v1;
            }
        }
    }
}

// QKV kernel: y 0..3 -> V dense (all rows); y 4..11 -> Q/K gathered (non-reset)
__global__ __launch_bounds__(256) void qkv_gemm_tc(
    const float* __restrict__ bq, const float* __restrict__ bk,
    const float* __restrict__ bv)
{
    const int y = blockIdx.y;
    if (y < 4) {
        const int nc = y * BN;
        tc_gemm_body<false>(g_xt, g_wvt, bv, g_qkv, DIM, QKV_LD,
                            blockIdx.x * BM, nc, 2 * DWM + nc, DIM / BK, BSZ);
    } else {
        const int q  = y - 4;          // 0..7
        const int zz = q >> 2;         // 0=Q, 1=K
        const int nc = (q & 3) * BN;
        const int nrows = g_nrows;
        if (blockIdx.x * BM >= nrows) return;
        const float* Bw = zz ? g_wkt : g_wqt;
        const float* bi = zz ? bk : bq;
        tc_gemm_body<true>(g_xt, Bw, bi, g_qkv, DIM, QKV_LD,
                           blockIdx.x * BM, nc, zz * DWM + nc, DIM / BK, nrows);
    }
}

__global__ __launch_bounds__(256) void out_gemm_tc(
    const float* __restrict__ bo, float* __restrict__ y)
{
    tc_gemm_body<false>(g_att, g_wot, bo, y, DWM, DIM,
                        blockIdx.x * BM, blockIdx.y * BN, blockIdx.y * BN,
                        DWM / BK, BSZ);
}

// ---------------- Attention kernel: one CTA per (permuted) batch row ----------
// blockIdx.x < g_nrows  -> heavy row b = g_rows[bid] (non-reset), full path.
// blockIdx.x >= g_nrows -> reset row: out = v_new exactly (early exit).
// Unroll 16 in both streaming phases (R16-proven).
__global__ __launch_bounds__(256) void attn_kernel(
    const float* __restrict__ wmK, const float* __restrict__ wmV,
    const void* __restrict__ validIn,
    const int* __restrict__ ptrIn)
{
    __shared__ float q_s[DWM];
    __shared__ float att_s[NH][WIN];
    __shared__ unsigned char valid_s[WIN];

    const int bid  = blockIdx.x;
    const int tid  = threadIdx.x;   // 256
    const int lane = tid & 31;
    const int warp = tid >> 5;      // 8 warps == 8 heads

    const int b  = g_rows[bid];
    const bool rs = (bid >= g_nrows);

    const float* qrow  = g_qkv + (size_t)b * QKV_LD;
    const float* knew  = qrow + DWM;
    const float* vnew  = qrow + 2 * DWM;

    if (rs) {
        float2 v0 = *(const float2*)(vnew + tid * 2);
        v0.x = __uint_as_float(f2tf32(v0.x));
        v0.y = __uint_as_float(f2tf32(v0.y));
        *(float2*)(g_att + (size_t)b * DWM + tid * 2) = v0;
        return;
    }

    const int mode = bool_mode((const unsigned char*)validIn);
    const int p = ptrIn[b];
    const float* Kbase = wmK + (size_t)b * WIN * DWM;
    const float* Vbase = wmV + (size_t)b * WIN * DWM;

    for (int i = tid; i < DWM; i += 256) q_s[i] = qrow[i];
    if (tid < WIN)
        valid_s[tid] = read_bool(validIn, (size_t)b * WIN + tid, mode) ? 1 : 0;
    __syncthreads();

    const float NEG_INF = __int_as_float(0xff800000);

    // ---- phase 1: logits, unroll 16 (uniform over stored K; p patched) ----
    {
        const int h = warp;
        float2 qv = *(const float2*)(q_s + h * HD + lane * 2);
        const float2* kp = (const float2*)(Kbase + h * HD + lane * 2);
        for (int w0 = 0; w0 < WIN; w0 += 16) {
            float s[16];
            #pragma unroll
            for (int u = 0; u < 16; ++u) {
                float2 kv = __ldcs(kp + (size_t)(w0 + u) * (DWM / 2));
                s[u] = kv.x * qv.x + kv.y * qv.y;
            }
            #pragma unroll
            for (int u = 0; u < 16; ++u) {
                #pragma unroll
                for (int o = 16; o > 0; o >>= 1)
                    s[u] += __shfl_xor_sync(0xffffffffu, s[u], o);
            }
            if (lane == 0) {
                #pragma unroll
                for (int u = 0; u < 16; ++u) {
                    int w = w0 + u;
                    bool val = (valid_s[w] != 0);
                    att_s[h][w] = val ? s[u] * ATT_SCALE : NEG_INF;
                }
            }
        }
        {
            float2 kv = *(const float2*)(knew + h * HD + lane * 2);
            float s = kv.x * qv.x + kv.y * qv.y;
            #pragma unroll
            for (int o = 16; o > 0; o >>= 1)
                s += __shfl_xor_sync(0xffffffffu, s, o);
            if (lane == 0) att_s[h][p] = s * ATT_SCALE;
        }
    }
    __syncthreads();

    // prefetch first V batch before softmax (independent of att_s values)
    const int d = tid * 2;
    const int h3 = tid >> 5;
    const float2* vp = (const float2*)(Vbase + d);
    float2 vv0[16];
    #pragma unroll
    for (int u = 0; u < 16; ++u)
        vv0[u] = __ldcs(vp + (size_t)u * (DWM / 2));

    // ---- phase 2: per-head softmax (warp h) ----
    {
        const int h = warp;
        float e[8];
        float m = NEG_INF;
        #pragma unroll
        for (int j = 0; j < 8; ++j) {
            e[j] = att_s[h][lane + 32 * j];
            m = fmaxf(m, e[j]);
        }
        #pragma unroll
        for (int o = 16; o > 0; o >>= 1)
            m = fmaxf(m, __shfl_xor_sync(0xffffffffu, m, o));
        float sum = 0.f;
        #pragma unroll
        for (int j = 0; j < 8; ++j) {
            e[j] = __expf(e[j] - m);
            sum += e[j];
        }
        #pragma unroll
        for (int o = 16; o > 0; o >>= 1)
            sum += __shfl_xor_sync(0xffffffffu, sum, o);
        float inv = (sum > 0.f) ? (1.0f / sum) : 0.f;
        #pragma unroll
        for (int j = 0; j < 8; ++j)
            att_s[h][lane + 32 * j] = e[j] * inv;
    }
    __syncthreads();

    // ---- phase 3: AV, unroll 16; correction for slot p ----
    {
        float ax = 0.f, ay = 0.f;
        #pragma unroll
        for (int u = 0; u < 16; ++u) {
            float pw = att_s[h3][u];
            ax = fmaf(pw, vv0[u].x, ax);
            ay = fmaf(pw, vv0[u].y, ay);
        }
        for (int w0 = 16; w0 < WIN; w0 += 16) {
            float2 vv[16];
            #pragma unroll
            for (int u = 0; u < 16; ++u)
                vv[u] = __ldcs(vp + (size_t)(w0 + u) * (DWM / 2));
            #pragma unroll
            for (int u = 0; u < 16; ++u) {
                float pw = att_s[h3][w0 + u];
                ax = fmaf(pw, vv[u].x, ax);
                ay = fmaf(pw, vv[u].y, ay);
            }
        }
        {
            float2 vold = *(const float2*)(Vbase + (size_t)p * DWM + d);
            float2 vn   = *(const float2*)(vnew + d);
            float pw = att_s[h3][p];
            ax = fmaf(pw, vn.x - vold.x, ax);
            ay = fmaf(pw, vn.y - vold.y, ay);
        }
        float2 o;
        o.x = __uint_as_float(f2tf32(ax));
        o.y = __uint_as_float(f2tf32(ay));
        *(float2*)(g_att + (size_t)b * DWM + d) = o;
    }
}

// ---------------- launcher ---------------------------------------------------
extern "C" void kernel_launch(void* const* d_in, const int* in_sizes, int n_in,
                              void* d_out, int out_size)
{
    const float* x     = (const float*)d_in[0];
    const void*  reset = d_in[1];
    const float* wmK   = (const float*)d_in[2];
    const float* wmV   = (const float*)d_in[3];
    const void*  valid = d_in[4];
    const int*   ptr   = (const int*)d_in[5];
    const float* Wq    = (const float*)d_in[6];
    const float* bq    = (const float*)d_in[7];
    const float* Wk    = (const float*)d_in[8];
    const float* bk    = (const float*)d_in[9];
    const float* Wv    = (const float*)d_in[10];
    const float* bv    = (const float*)d_in[11];
    const float* Wo    = (const float*)d_in[12];
    const float* bo    = (const float*)d_in[13];
    float*       y     = (float*)d_out;

    cudaFuncSetAttribute(qkv_gemm_tc, cudaFuncAttributeMaxDynamicSharedMemorySize, TCSM_BYTES);
    cudaFuncSetAttribute(out_gemm_tc, cudaFuncAttributeMaxDynamicSharedMemorySize, TCSM_BYTES);

    // fused: tf32 pre-round (blocks 0..2047) + row compaction (block 2048)
    convert_kernel<<<2049, 256>>>(x, Wq, Wk, Wv, Wo, reset, valid);

    dim3 gQKV(BSZ / BM, 12);            // 16 x 12; Q/K tail tiles self-disable
    qkv_gemm_tc<<<gQKV, 256, TCSM_BYTES>>>(bq, bk, bv);

    attn_kernel<<<BSZ, 256>>>(wmK, wmV, valid, ptr);

    dim3 gOut(BSZ / BM, DIM / BN);      // 16 x 8 = 128 CTAs
    out_gemm_tc<<<gOut, 256, TCSM_BYTES>>>(bo, y);
}